// round 1
// baseline (speedup 1.0000x reference)
#include <cuda_runtime.h>
#include <math.h>

#define NN 100000
#define DD 128
#define ND (NN * DD)

// ---------------- scratch (allocation-free: __device__ globals) ----------------
__device__ float  g_deg[2][NN];
__device__ float  g_norm[2][NN];
__device__ float  g_cur[2][ND];      // current features per graph (51.2 MB each)
__device__ float  g_agg[2][ND];      // aggregation buffer per graph
__device__ double g_sum[2][DD];
__device__ double g_sumsq[2][DD];
__device__ float  g_mean[2][DD];
__device__ float  g_inv[2][DD];

// ---------------- init: zero deg, agg, stats ----------------
__global__ void k_init(int g) {
    int idx = blockIdx.x * blockDim.x + threadIdx.x;
    int stride = gridDim.x * blockDim.x;
    float4 z = make_float4(0.f, 0.f, 0.f, 0.f);
    float4* agg4 = reinterpret_cast<float4*>(g_agg[g]);
    for (int i = idx; i < ND / 4; i += stride) agg4[i] = z;
    for (int i = idx; i < NN; i += stride) g_deg[g][i] = 0.f;
    if (idx < DD) { g_sum[g][idx] = 0.0; g_sumsq[g][idx] = 0.0; }
}

// ---------------- degree count + symmetric norm ----------------
__global__ void k_count(int g, const int* __restrict__ dst, int E) {
    int i = blockIdx.x * blockDim.x + threadIdx.x;
    if (i < E) atomicAdd(&g_deg[g][dst[i]], 1.f);
}

__global__ void k_norm(int g) {
    int i = blockIdx.x * blockDim.x + threadIdx.x;
    if (i < NN) g_norm[g][i] = rsqrtf(fmaxf(g_deg[g][i], 1.f));
}

// ---------------- edge scatter: agg[dst] += feat[src] * norm[src] ----------------
// one warp per edge; lane handles 4 consecutive floats (float4 gather, 4 RED adds)
__global__ void k_scatter(int g, const float* __restrict__ feat_in, int use_cur,
                          const int* __restrict__ src, const int* __restrict__ dst, int E) {
    int wid = (blockIdx.x * blockDim.x + threadIdx.x) >> 5;
    if (wid >= E) return;
    int lane = threadIdx.x & 31;
    const float* feat = use_cur ? g_cur[g] : feat_in;
    int s = __ldg(&src[wid]);
    int d = __ldg(&dst[wid]);
    float sc = g_norm[g][s];
    float4 v = reinterpret_cast<const float4*>(feat + (size_t)s * DD)[lane];
    float* ad = &g_agg[g][(size_t)d * DD + lane * 4];
    atomicAdd(ad + 0, v.x * sc);
    atomicAdd(ad + 1, v.y * sc);
    atomicAdd(ad + 2, v.z * sc);
    atomicAdd(ad + 3, v.w * sc);
}

// ---------------- fused layer: h = 0.9*agg*norm + 0.1*feat0; out = relu((1-b)h + b*hW + bias)
// also zeroes agg rows in-place so the next layer's scatter sees a clean buffer.
__global__ void __launch_bounds__(256) k_layer(int g, const float* __restrict__ feat0,
                                               const float* __restrict__ W,
                                               const float* __restrict__ bias,
                                               float beta) {
    __shared__ float hs[64][DD];   // 32 KB
    int row0 = blockIdx.x * 64;
    int tid = threadIdx.x;

    // stage h tile (vectorized), zero agg behind us
    float4* agg4 = reinterpret_cast<float4*>(g_agg[g]);
    const float4* f04 = reinterpret_cast<const float4*>(feat0);
    for (int i = tid; i < 64 * 32; i += 256) {
        int r = i >> 5, c4 = i & 31;
        int n = row0 + r;
        float4 h4 = make_float4(0.f, 0.f, 0.f, 0.f);
        if (n < NN) {
            size_t off = (size_t)n * 32 + c4;
            float4 a = agg4[off];
            agg4[off] = make_float4(0.f, 0.f, 0.f, 0.f);
            float4 f = f04[off];
            float nr = g_norm[g][n];
            h4.x = 0.9f * a.x * nr + 0.1f * f.x;
            h4.y = 0.9f * a.y * nr + 0.1f * f.y;
            h4.z = 0.9f * a.z * nr + 0.1f * f.z;
            h4.w = 0.9f * a.w * nr + 0.1f * f.w;
        }
        reinterpret_cast<float4*>(&hs[r][0])[c4] = h4;
    }
    __syncthreads();

    // GEMM: warp w -> rows [8w, 8w+8); lane -> cols lane + 32j, j=0..3
    int w = tid >> 5, lane = tid & 31;
    float acc[8][4];
#pragma unroll
    for (int r = 0; r < 8; r++)
#pragma unroll
        for (int j = 0; j < 4; j++) acc[r][j] = 0.f;

#pragma unroll 4
    for (int k = 0; k < DD; k++) {
        float wv0 = __ldg(&W[k * DD + lane]);
        float wv1 = __ldg(&W[k * DD + lane + 32]);
        float wv2 = __ldg(&W[k * DD + lane + 64]);
        float wv3 = __ldg(&W[k * DD + lane + 96]);
#pragma unroll
        for (int r = 0; r < 8; r++) {
            float hv = hs[w * 8 + r][k];
            acc[r][0] = fmaf(hv, wv0, acc[r][0]);
            acc[r][1] = fmaf(hv, wv1, acc[r][1]);
            acc[r][2] = fmaf(hv, wv2, acc[r][2]);
            acc[r][3] = fmaf(hv, wv3, acc[r][3]);
        }
    }

    float ob = 1.f - beta;
#pragma unroll
    for (int r = 0; r < 8; r++) {
        int n = row0 + w * 8 + r;
        if (n >= NN) continue;
#pragma unroll
        for (int j = 0; j < 4; j++) {
            int c = lane + 32 * j;
            float h = hs[w * 8 + r][c];
            float o = ob * h + beta * acc[r][j] + __ldg(&bias[c]);
            g_cur[g][(size_t)n * DD + c] = fmaxf(o, 0.f);
        }
    }
}

// ---------------- per-column stats (sum, sumsq) ----------------
__global__ void k_stats(int g) {
    __shared__ float ssum[256], ssq[256];
    int c = threadIdx.x & 127;
    int half = threadIdx.x >> 7;
    int row0 = blockIdx.x * 256;
    int rend = row0 + 256;
    if (rend > NN) rend = NN;
    float s = 0.f, q = 0.f;
    for (int r = row0 + half; r < rend; r += 2) {
        float v = g_cur[g][(size_t)r * DD + c];
        s += v;
        q += v * v;
    }
    ssum[threadIdx.x] = s;
    ssq[threadIdx.x] = q;
    __syncthreads();
    if (half == 0) {
        double ts = (double)ssum[c] + (double)ssum[c + 128];
        double tq = (double)ssq[c] + (double)ssq[c + 128];
        atomicAdd(&g_sum[g][c], ts);
        atomicAdd(&g_sumsq[g][c], tq);
    }
}

__global__ void k_finalize(int g) {
    int c = threadIdx.x;
    if (c < DD) {
        double mean = g_sum[g][c] / (double)NN;
        double var = (g_sumsq[g][c] - (double)NN * mean * mean) / (double)(NN - 1);
        if (var < 0.0) var = 0.0;
        float sd = (float)sqrt(var);
        g_mean[g][c] = (float)mean;
        g_inv[g][c] = 1.f / fmaxf(sd, 1e-12f);
    }
}

__global__ void k_write(int g, float* __restrict__ out) {
    int idx = blockIdx.x * blockDim.x + threadIdx.x;
    int stride = gridDim.x * blockDim.x;
    for (int i = idx; i < ND; i += stride) {
        int c = i & 127;
        out[i] = (g_cur[g][i] - g_mean[g][c]) * g_inv[g][c];
    }
}

// ---------------- launch ----------------
extern "C" void kernel_launch(void* const* d_in, const int* in_sizes, int n_in,
                              void* d_out, int out_size) {
    const float* feat[2] = {(const float*)d_in[0], (const float*)d_in[1]};
    const int* srcs[2] = {(const int*)d_in[2], (const int*)d_in[4]};
    const int* dsts[2] = {(const int*)d_in[3], (const int*)d_in[5]};
    const float* weights = (const float*)d_in[6];
    const float* biases = (const float*)d_in[7];
    int E = in_sizes[2];
    float* out = (float*)d_out;

    int scatter_blocks = (E + 7) / 8;          // 8 warps (256 threads) per block
    int layer_blocks = (NN + 63) / 64;
    int stats_blocks = (NN + 255) / 256;

    for (int g = 0; g < 2; g++) {
        k_init<<<2048, 256>>>(g);
        k_count<<<(E + 255) / 256, 256>>>(g, dsts[g], E);
        k_norm<<<(NN + 255) / 256, 256>>>(g);
        for (int l = 0; l < 4; l++) {
            float beta = logf(1.0f / (float)(l + 1) + 1.0f);
            k_scatter<<<scatter_blocks, 256>>>(g, feat[g], (l > 0) ? 1 : 0,
                                               srcs[g], dsts[g], E);
            k_layer<<<layer_blocks, 256>>>(g, feat[g], weights + (size_t)l * DD * DD,
                                           biases + (size_t)l * DD, beta);
        }
        k_stats<<<stats_blocks, 256>>>(g);
        k_finalize<<<1, DD>>>(g);
        k_write<<<2048, 256>>>(g, out + (size_t)g * ND);
    }
}

// round 3
// speedup vs baseline: 3.1203x; 3.1203x over previous
#include <cuda_runtime.h>
#include <math.h>

#define NN 100000
#define DD 128
#define ND (NN * DD)
#define EMAX 1600000

// ---------------- scratch (allocation-free: __device__ globals) ----------------
__device__ int    g_deg[2][NN];
__device__ float  g_norm[2][NN];
__device__ int    g_rowptr[2][NN + 1];
__device__ int    g_cursor[2][NN];
__device__ int    g_col[2][EMAX];        // src ids grouped by dst
__device__ float  g_buf[2][2][ND];       // ping-pong feature buffers per graph
__device__ double g_sum[2][DD];
__device__ double g_sumsq[2][DD];
__device__ float  g_mean[2][DD];
__device__ float  g_inv[2][DD];

// ---------------- init: zero deg + stats ----------------
__global__ void k_init(int g) {
    int idx = blockIdx.x * blockDim.x + threadIdx.x;
    int stride = gridDim.x * blockDim.x;
    for (int i = idx; i < NN; i += stride) g_deg[g][i] = 0;
    if (idx < DD) { g_sum[g][idx] = 0.0; g_sumsq[g][idx] = 0.0; }
}

// ---------------- degree histogram ----------------
__global__ void k_count(int g, const int* __restrict__ dst, int E) {
    int i = blockIdx.x * blockDim.x + threadIdx.x;
    if (i < E) atomicAdd(&g_deg[g][dst[i]], 1);
}

// ---------------- norm = rsqrt(max(deg,1)) ----------------
__global__ void k_norm(int g) {
    int i = blockIdx.x * blockDim.x + threadIdx.x;
    if (i < NN) g_norm[g][i] = rsqrtf(fmaxf((float)g_deg[g][i], 1.f));
}

// ---------------- single-block exclusive scan of deg -> rowptr (+ cursor copy) --
__global__ void __launch_bounds__(1024) k_scan(int g) {
    __shared__ int part[1024];
    int t = threadIdx.x;
    const int CH = (NN + 1023) / 1024;           // 98
    int beg = t * CH;
    int end = beg + CH; if (end > NN) end = NN;
    int s = 0;
    for (int i = beg; i < end; i++) s += g_deg[g][i];
    part[t] = s;
    __syncthreads();
    if (t == 0) {
        int run = 0;
        for (int i = 0; i < 1024; i++) { int v = part[i]; part[i] = run; run += v; }
        g_rowptr[g][NN] = run;
    }
    __syncthreads();
    int run = part[t];
    for (int i = beg; i < end; i++) {
        g_rowptr[g][i] = run;
        g_cursor[g][i] = run;
        run += g_deg[g][i];
    }
}

// ---------------- CSR fill: col grouped by dst ----------------
__global__ void k_fill(int g, const int* __restrict__ src, const int* __restrict__ dst, int E) {
    int i = blockIdx.x * blockDim.x + threadIdx.x;
    if (i < E) {
        int pos = atomicAdd(&g_cursor[g][dst[i]], 1);
        g_col[g][pos] = src[i];
    }
}

// ---------------- fused gather + GCNII layer (reads src_feat, writes dst_feat) --
__global__ void __launch_bounds__(256) k_layer(int g, const float* __restrict__ src_feat,
                                               float* __restrict__ dst_feat,
                                               const float* __restrict__ feat0,
                                               const float* __restrict__ W,
                                               const float* __restrict__ bias, float beta) {
    __shared__ float hs[64][DD];   // 32 KB
    int row0 = blockIdx.x * 64;
    int w = threadIdx.x >> 5, lane = threadIdx.x & 31;

    const float4* feat4 = reinterpret_cast<const float4*>(src_feat);
    const float4* f04 = reinterpret_cast<const float4*>(feat0);
    const int* __restrict__ rp = g_rowptr[g];
    const int* __restrict__ col = g_col[g];
    const float* __restrict__ nrm = g_norm[g];

    for (int r8 = 0; r8 < 8; r8++) {
        int r = w * 8 + r8;
        int n = row0 + r;
        float4 acc = make_float4(0.f, 0.f, 0.f, 0.f);
        if (n < NN) {
            int beg = __ldg(&rp[n]);
            int end = __ldg(&rp[n + 1]);
            int e = beg;
            for (; e + 1 < end; e += 2) {
                int s0 = __ldg(&col[e]);
                int s1 = __ldg(&col[e + 1]);
                float c0 = __ldg(&nrm[s0]);
                float c1 = __ldg(&nrm[s1]);
                float4 v0 = feat4[(size_t)s0 * 32 + lane];
                float4 v1 = feat4[(size_t)s1 * 32 + lane];
                acc.x += v0.x * c0 + v1.x * c1;
                acc.y += v0.y * c0 + v1.y * c1;
                acc.z += v0.z * c0 + v1.z * c1;
                acc.w += v0.w * c0 + v1.w * c1;
            }
            if (e < end) {
                int s0 = __ldg(&col[e]);
                float c0 = __ldg(&nrm[s0]);
                float4 v0 = feat4[(size_t)s0 * 32 + lane];
                acc.x += v0.x * c0;
                acc.y += v0.y * c0;
                acc.z += v0.z * c0;
                acc.w += v0.w * c0;
            }
            float nr = nrm[n];
            float4 f = f04[(size_t)n * 32 + lane];
            acc.x = 0.9f * acc.x * nr + 0.1f * f.x;
            acc.y = 0.9f * acc.y * nr + 0.1f * f.y;
            acc.z = 0.9f * acc.z * nr + 0.1f * f.z;
            acc.w = 0.9f * acc.w * nr + 0.1f * f.w;
        }
        reinterpret_cast<float4*>(&hs[r][0])[lane] = acc;
    }
    __syncthreads();

    float acc[8][4];
#pragma unroll
    for (int r = 0; r < 8; r++)
#pragma unroll
        for (int j = 0; j < 4; j++) acc[r][j] = 0.f;

#pragma unroll 4
    for (int k = 0; k < DD; k++) {
        float wv0 = __ldg(&W[k * DD + lane]);
        float wv1 = __ldg(&W[k * DD + lane + 32]);
        float wv2 = __ldg(&W[k * DD + lane + 64]);
        float wv3 = __ldg(&W[k * DD + lane + 96]);
#pragma unroll
        for (int r = 0; r < 8; r++) {
            float hv = hs[w * 8 + r][k];
            acc[r][0] = fmaf(hv, wv0, acc[r][0]);
            acc[r][1] = fmaf(hv, wv1, acc[r][1]);
            acc[r][2] = fmaf(hv, wv2, acc[r][2]);
            acc[r][3] = fmaf(hv, wv3, acc[r][3]);
        }
    }

    float ob = 1.f - beta;
#pragma unroll
    for (int r = 0; r < 8; r++) {
        int n = row0 + w * 8 + r;
        if (n >= NN) continue;
#pragma unroll
        for (int j = 0; j < 4; j++) {
            int c = lane + 32 * j;
            float h = hs[w * 8 + r][c];
            float o = ob * h + beta * acc[r][j] + __ldg(&bias[c]);
            dst_feat[(size_t)n * DD + c] = fmaxf(o, 0.f);
        }
    }
}

// ---------------- per-column stats (sum, sumsq) ----------------
__global__ void k_stats(int g, const float* __restrict__ feat) {
    __shared__ float ssum[256], ssq[256];
    int c = threadIdx.x & 127;
    int half = threadIdx.x >> 7;
    int row0 = blockIdx.x * 256;
    int rend = row0 + 256;
    if (rend > NN) rend = NN;
    float s = 0.f, q = 0.f;
    for (int r = row0 + half; r < rend; r += 2) {
        float v = feat[(size_t)r * DD + c];
        s += v;
        q += v * v;
    }
    ssum[threadIdx.x] = s;
    ssq[threadIdx.x] = q;
    __syncthreads();
    if (half == 0) {
        double ts = (double)ssum[c] + (double)ssum[c + 128];
        double tq = (double)ssq[c] + (double)ssq[c + 128];
        atomicAdd(&g_sum[g][c], ts);
        atomicAdd(&g_sumsq[g][c], tq);
    }
}

__global__ void k_finalize(int g) {
    int c = threadIdx.x;
    if (c < DD) {
        double mean = g_sum[g][c] / (double)NN;
        double var = (g_sumsq[g][c] - (double)NN * mean * mean) / (double)(NN - 1);
        if (var < 0.0) var = 0.0;
        float sd = (float)sqrt(var);
        g_mean[g][c] = (float)mean;
        g_inv[g][c] = 1.f / fmaxf(sd, 1e-12f);
    }
}

__global__ void k_write(int g, const float* __restrict__ feat, float* __restrict__ out) {
    int idx = blockIdx.x * blockDim.x + threadIdx.x;
    int stride = gridDim.x * blockDim.x;
    for (int i = idx; i < ND; i += stride) {
        int c = i & 127;
        out[i] = (feat[i] - g_mean[g][c]) * g_inv[g][c];
    }
}

// ---------------- launch ----------------
extern "C" void kernel_launch(void* const* d_in, const int* in_sizes, int n_in,
                              void* d_out, int out_size) {
    const float* feat[2] = {(const float*)d_in[0], (const float*)d_in[1]};
    const int* srcs[2] = {(const int*)d_in[2], (const int*)d_in[4]};
    const int* dsts[2] = {(const int*)d_in[3], (const int*)d_in[5]};
    const float* weights = (const float*)d_in[6];
    const float* biases = (const float*)d_in[7];
    int E = in_sizes[2];
    float* out = (float*)d_out;

    static float* buf_addr[2][2] = {{nullptr, nullptr}, {nullptr, nullptr}};
    if (!buf_addr[0][0]) {
        void* p = nullptr;
        cudaGetSymbolAddress(&p, g_buf);
        float* base = (float*)p;
        for (int g = 0; g < 2; g++)
            for (int b = 0; b < 2; b++)
                buf_addr[g][b] = base + ((size_t)g * 2 + b) * (size_t)ND;
    }

    int eb = (E + 255) / 256;
    int layer_blocks = (NN + 63) / 64;
    int stats_blocks = (NN + 255) / 256;

    for (int g = 0; g < 2; g++) {
        k_init<<<256, 256>>>(g);
        k_count<<<eb, 256>>>(g, dsts[g], E);
        k_norm<<<(NN + 255) / 256, 256>>>(g);
        k_scan<<<1, 1024>>>(g);
        k_fill<<<eb, 256>>>(g, srcs[g], dsts[g], E);
        for (int l = 0; l < 4; l++) {
            float beta = logf(1.0f / (float)(l + 1) + 1.0f);
            const float* sf = (l == 0) ? feat[g] : buf_addr[g][(l - 1) & 1];
            float* df = buf_addr[g][l & 1];
            k_layer<<<layer_blocks, 256>>>(g, sf, df, feat[g],
                                           weights + (size_t)l * DD * DD,
                                           biases + (size_t)l * DD, beta);
        }
        const float* fin = buf_addr[g][1];   // layer 3 writes buf[1]
        k_stats<<<stats_blocks, 256>>>(g, fin);
        k_finalize<<<1, DD>>>(g);
        k_write<<<2048, 256>>>(g, fin, out + (size_t)g * ND);
    }
}

// round 5
// speedup vs baseline: 3.7247x; 1.1937x over previous
#include <cuda_runtime.h>
#include <math.h>

#define NN 100000
#define DD 128
#define ND (NN * DD)
#define EMAX 1600000
#define NPART 782           // ceil(100000 / 128)

// ---------------- scratch (allocation-free: __device__ globals) ----------------
__device__ int    g_deg[2][NN];
__device__ float  g_norm[2][NN];
__device__ int    g_rowptr[2][NN + 1];
__device__ int    g_cursor[2][NN];
__device__ int    g_part[2][NPART];
__device__ int    g_col[2][EMAX];        // src ids grouped by dst
__device__ float  g_buf[2][2][ND];       // ping-pong feature buffers per graph
__device__ double g_sum[2][DD];
__device__ double g_sumsq[2][DD];
__device__ float  g_mean[2][DD];
__device__ float  g_inv[2][DD];

// ---------------- init: zero deg + stats ----------------
__global__ void k_init(int g) {
    int idx = blockIdx.x * blockDim.x + threadIdx.x;
    int stride = gridDim.x * blockDim.x;
    for (int i = idx; i < NN; i += stride) g_deg[g][i] = 0;
    if (idx < DD) { g_sum[g][idx] = 0.0; g_sumsq[g][idx] = 0.0; }
}

// ---------------- degree histogram ----------------
__global__ void k_count(int g, const int* __restrict__ dst, int E) {
    int i = blockIdx.x * blockDim.x + threadIdx.x;
    if (i < E) atomicAdd(&g_deg[g][dst[i]], 1);
}

// ---------------- scan stage 1: per-block (128 elems) partial sums ----------------
__global__ void __launch_bounds__(128) k_scan1(int g) {
    __shared__ int wsum[4];
    int t = threadIdx.x;
    int i = blockIdx.x * 128 + t;
    int v = (i < NN) ? g_deg[g][i] : 0;
    int x = v;
    for (int o = 16; o > 0; o >>= 1) x += __shfl_down_sync(0xffffffffu, x, o);
    if ((t & 31) == 0) wsum[t >> 5] = x;
    __syncthreads();
    if (t == 0) g_part[g][blockIdx.x] = wsum[0] + wsum[1] + wsum[2] + wsum[3];
}

// ---------------- scan stage 2: exclusive scan of NPART partials (1 block) -------
__global__ void __launch_bounds__(1024) k_scan2(int g) {
    __shared__ int sm[1024];
    int t = threadIdx.x;
    sm[t] = (t < NPART) ? g_part[g][t] : 0;
    __syncthreads();
    for (int off = 1; off < 1024; off <<= 1) {
        int v = sm[t];
        int add = (t >= off) ? sm[t - off] : 0;
        __syncthreads();
        sm[t] = v + add;
        __syncthreads();
    }
    if (t < NPART) g_part[g][t] = (t == 0) ? 0 : sm[t - 1];
    if (t == 0) g_rowptr[g][NN] = sm[NPART - 1];
}

// ---------------- scan stage 3: block-local scan + offset; also compute norm -----
__global__ void __launch_bounds__(128) k_scan3(int g) {
    __shared__ int wsum[4], woff[4];
    int t = threadIdx.x;
    int lane = t & 31, wid = t >> 5;
    int i = blockIdx.x * 128 + t;
    int v = (i < NN) ? g_deg[g][i] : 0;
    int x = v;
    for (int o = 1; o < 32; o <<= 1) {
        int y = __shfl_up_sync(0xffffffffu, x, o);
        if (lane >= o) x += y;
    }
    if (lane == 31) wsum[wid] = x;
    __syncthreads();
    if (t == 0) {
        int r = 0;
        for (int k = 0; k < 4; k++) { woff[k] = r; r += wsum[k]; }
    }
    __syncthreads();
    int excl = x - v + woff[wid] + g_part[g][blockIdx.x];
    if (i < NN) {
        g_rowptr[g][i] = excl;
        g_cursor[g][i] = excl;
        g_norm[g][i] = rsqrtf(fmaxf((float)v, 1.f));
    }
}

// ---------------- CSR fill: col grouped by dst ----------------
__global__ void k_fill(int g, const int* __restrict__ src, const int* __restrict__ dst, int E) {
    int i = blockIdx.x * blockDim.x + threadIdx.x;
    if (i < E) {
        int pos = atomicAdd(&g_cursor[g][dst[i]], 1);
        g_col[g][pos] = src[i];
    }
}

// ---------------- fused gather + GCNII layer (reads src_feat, writes dst_feat) --
__global__ void __launch_bounds__(256) k_layer(int g, const float* __restrict__ src_feat,
                                               float* __restrict__ dst_feat,
                                               const float* __restrict__ feat0,
                                               const float* __restrict__ W,
                                               const float* __restrict__ bias, float beta) {
    __shared__ float hs[64][DD];   // 32 KB
    int row0 = blockIdx.x * 64;
    int w = threadIdx.x >> 5, lane = threadIdx.x & 31;

    const float4* feat4 = reinterpret_cast<const float4*>(src_feat);
    const float4* f04 = reinterpret_cast<const float4*>(feat0);
    const int* __restrict__ rp = g_rowptr[g];
    const int* __restrict__ col = g_col[g];
    const float* __restrict__ nrm = g_norm[g];

    for (int r8 = 0; r8 < 8; r8++) {
        int r = w * 8 + r8;
        int n = row0 + r;
        float4 acc = make_float4(0.f, 0.f, 0.f, 0.f);
        if (n < NN) {
            int beg = __ldg(&rp[n]);
            int end = __ldg(&rp[n + 1]);
            int e = beg;
            for (; e + 1 < end; e += 2) {
                int s0 = __ldg(&col[e]);
                int s1 = __ldg(&col[e + 1]);
                float c0 = __ldg(&nrm[s0]);
                float c1 = __ldg(&nrm[s1]);
                float4 v0 = feat4[(size_t)s0 * 32 + lane];
                float4 v1 = feat4[(size_t)s1 * 32 + lane];
                acc.x += v0.x * c0 + v1.x * c1;
                acc.y += v0.y * c0 + v1.y * c1;
                acc.z += v0.z * c0 + v1.z * c1;
                acc.w += v0.w * c0 + v1.w * c1;
            }
            if (e < end) {
                int s0 = __ldg(&col[e]);
                float c0 = __ldg(&nrm[s0]);
                float4 v0 = feat4[(size_t)s0 * 32 + lane];
                acc.x += v0.x * c0;
                acc.y += v0.y * c0;
                acc.z += v0.z * c0;
                acc.w += v0.w * c0;
            }
            float nr = nrm[n];
            float4 f = f04[(size_t)n * 32 + lane];
            acc.x = 0.9f * acc.x * nr + 0.1f * f.x;
            acc.y = 0.9f * acc.y * nr + 0.1f * f.y;
            acc.z = 0.9f * acc.z * nr + 0.1f * f.z;
            acc.w = 0.9f * acc.w * nr + 0.1f * f.w;
        }
        reinterpret_cast<float4*>(&hs[r][0])[lane] = acc;
    }
    __syncthreads();

    float acc[8][4];
#pragma unroll
    for (int r = 0; r < 8; r++)
#pragma unroll
        for (int j = 0; j < 4; j++) acc[r][j] = 0.f;

#pragma unroll 4
    for (int k = 0; k < DD; k++) {
        float wv0 = __ldg(&W[k * DD + lane]);
        float wv1 = __ldg(&W[k * DD + lane + 32]);
        float wv2 = __ldg(&W[k * DD + lane + 64]);
        float wv3 = __ldg(&W[k * DD + lane + 96]);
#pragma unroll
        for (int r = 0; r < 8; r++) {
            float hv = hs[w * 8 + r][k];
            acc[r][0] = fmaf(hv, wv0, acc[r][0]);
            acc[r][1] = fmaf(hv, wv1, acc[r][1]);
            acc[r][2] = fmaf(hv, wv2, acc[r][2]);
            acc[r][3] = fmaf(hv, wv3, acc[r][3]);
        }
    }

    float ob = 1.f - beta;
#pragma unroll
    for (int r = 0; r < 8; r++) {
        int n = row0 + w * 8 + r;
        if (n >= NN) continue;
#pragma unroll
        for (int j = 0; j < 4; j++) {
            int c = lane + 32 * j;
            float h = hs[w * 8 + r][c];
            float o = ob * h + beta * acc[r][j] + __ldg(&bias[c]);
            dst_feat[(size_t)n * DD + c] = fmaxf(o, 0.f);
        }
    }
}

// ---------------- per-column stats (sum, sumsq) ----------------
__global__ void k_stats(int g, const float* __restrict__ feat) {
    __shared__ float ssum[256], ssq[256];
    int c = threadIdx.x & 127;
    int half = threadIdx.x >> 7;
    int row0 = blockIdx.x * 256;
    int rend = row0 + 256;
    if (rend > NN) rend = NN;
    float s = 0.f, q = 0.f;
    for (int r = row0 + half; r < rend; r += 2) {
        float v = feat[(size_t)r * DD + c];
        s += v;
        q += v * v;
    }
    ssum[threadIdx.x] = s;
    ssq[threadIdx.x] = q;
    __syncthreads();
    if (half == 0) {
        double ts = (double)ssum[c] + (double)ssum[c + 128];
        double tq = (double)ssq[c] + (double)ssq[c + 128];
        atomicAdd(&g_sum[g][c], ts);
        atomicAdd(&g_sumsq[g][c], tq);
    }
}

__global__ void k_finalize(int g) {
    int c = threadIdx.x;
    if (c < DD) {
        double mean = g_sum[g][c] / (double)NN;
        double var = (g_sumsq[g][c] - (double)NN * mean * mean) / (double)(NN - 1);
        if (var < 0.0) var = 0.0;
        float sd = (float)sqrt(var);
        g_mean[g][c] = (float)mean;
        g_inv[g][c] = 1.f / fmaxf(sd, 1e-12f);
    }
}

__global__ void k_write(int g, const float* __restrict__ feat, float* __restrict__ out) {
    int idx = blockIdx.x * blockDim.x + threadIdx.x;
    int stride = gridDim.x * blockDim.x;
    for (int i = idx; i < ND; i += stride) {
        int c = i & 127;
        out[i] = (feat[i] - g_mean[g][c]) * g_inv[g][c];
    }
}

// ---------------- launch (single stream — capture-safe) ----------------
extern "C" void kernel_launch(void* const* d_in, const int* in_sizes, int n_in,
                              void* d_out, int out_size) {
    const float* feat[2] = {(const float*)d_in[0], (const float*)d_in[1]};
    const int* srcs[2] = {(const int*)d_in[2], (const int*)d_in[4]};
    const int* dsts[2] = {(const int*)d_in[3], (const int*)d_in[5]};
    const float* weights = (const float*)d_in[6];
    const float* biases = (const float*)d_in[7];
    int E = in_sizes[2];
    float* out = (float*)d_out;

    static float* buf_addr[2][2] = {{nullptr, nullptr}, {nullptr, nullptr}};
    if (!buf_addr[0][0]) {
        void* p = nullptr;
        cudaGetSymbolAddress(&p, g_buf);
        float* base = (float*)p;
        for (int g = 0; g < 2; g++)
            for (int b = 0; b < 2; b++)
                buf_addr[g][b] = base + ((size_t)g * 2 + b) * (size_t)ND;
    }

    int eb = (E + 255) / 256;
    int layer_blocks = (NN + 63) / 64;
    int stats_blocks = (NN + 255) / 256;

    for (int g = 0; g < 2; g++) {
        k_init<<<256, 256>>>(g);
        k_count<<<eb, 256>>>(g, dsts[g], E);
        k_scan1<<<NPART, 128>>>(g);
        k_scan2<<<1, 1024>>>(g);
        k_scan3<<<NPART, 128>>>(g);
        k_fill<<<eb, 256>>>(g, srcs[g], dsts[g], E);
        for (int l = 0; l < 4; l++) {
            float beta = logf(1.0f / (float)(l + 1) + 1.0f);
            const float* sf = (l == 0) ? feat[g] : buf_addr[g][(l - 1) & 1];
            float* df = buf_addr[g][l & 1];
            k_layer<<<layer_blocks, 256>>>(g, sf, df, feat[g],
                                           weights + (size_t)l * DD * DD,
                                           biases + (size_t)l * DD, beta);
        }
        const float* fin = buf_addr[g][1];   // layer 3 writes buf[1]
        k_stats<<<stats_blocks, 256>>>(g, fin);
        k_finalize<<<1, DD>>>(g);
        k_write<<<1024, 256>>>(g, fin, out + (size_t)g * ND);
    }
}